// round 1
// baseline (speedup 1.0000x reference)
#include <cuda_runtime.h>
#include <math.h>

#define CB 2
#define CN 512
#define CF 1024
#define CH 4
#define CDH 256
#define CAH 256
#define CHID 512
#define COUT 128
#define CNCLS 10
#define CNN (CN*CN)
#define RSEL 52429u   /* NN - int(0.8*NN) = 262144 - 209715 */

// ---------------- scratch (static device memory; no allocations) ----------------
__device__ float g_hp[CB*CN*CF];
__device__ float g_si[CB*CH*CN];
__device__ float g_sj[CB*CH*CN];
__device__ float g_alpha[CB*CH*CN*CN];
__device__ float g_nf[CB*CN*CF];
__device__ float g_pi[CB*CN*CAH];
__device__ float g_pj[CB*CN*CAH];
__device__ float g_edge[CB*CNN];
__device__ float g_cm[CB*CNN];
__device__ float g_h1[CB*CN*CF];
__device__ float g_h2[CB*CN*CHID];
__device__ float g_h3[CB*CN*CHID];
__device__ float g_h4[CB*CN*COUT];
__device__ float g_feat[CB*COUT];
__device__ unsigned g_hist[CB*65536];
__device__ unsigned g_selhi[CB];
__device__ unsigned g_rank2[CB];
__device__ unsigned g_maxkey[CB];
__device__ float g_thr[CB];
__device__ float g_msum[CB];
__device__ float g_bs1[CHID], g_bq1[CHID], g_sc1[CHID], g_sh1[CHID];
__device__ float g_bs2[COUT], g_bq2[COUT], g_sc2[COUT], g_sh2[COUT];

// ---------------- helpers ----------------
__device__ __forceinline__ unsigned key_of(float x) {
    unsigned u = __float_as_uint(x);
    return (u & 0x80000000u) ? ~u : (u | 0x80000000u);
}
__device__ __forceinline__ float key_inv(unsigned key) {
    unsigned u = (key & 0x80000000u) ? (key ^ 0x80000000u) : ~key;
    return __uint_as_float(u);
}

// ---------------- zero scratch (must run every launch; graph replays) ----------------
__global__ void k_zero() {
    int i = blockIdx.x * 256 + threadIdx.x;       // grid = 512 blocks -> 131072 threads
    g_hist[i] = 0;
    if (i < CHID) { g_bs1[i] = 0.f; g_bq1[i] = 0.f; }
    if (i < COUT) { g_bs2[i] = 0.f; g_bq2[i] = 0.f; }
    if (i < CB)   { g_msum[i] = 0.f; g_maxkey[i] = 0u; }
}

// ---------------- tiled SGEMM, C[m,n] = sum_k A[m,k]*B[n,k]  (both K-contiguous) -----
__global__ void __launch_bounds__(256) gemm_nt(
    const float* __restrict__ A, const float* __restrict__ Bm, float* __restrict__ C,
    int M, int Nd, int K, int lda, int ldb, int ldc)
{
    __shared__ __align__(16) float As[16][68];
    __shared__ __align__(16) float Bs[16][68];
    int t = threadIdx.x;
    int m0 = blockIdx.y * 64, n0 = blockIdx.x * 64;
    int tx = t & 15, ty = t >> 4;
    int ka = t & 15, ra = t >> 4;
    float acc[4][4] = {};
    for (int k0 = 0; k0 < K; k0 += 16) {
#pragma unroll
        for (int r = 0; r < 4; r++) {
            As[ka][ra + 16*r] = A[(size_t)(m0 + ra + 16*r) * lda + k0 + ka];
            Bs[ka][ra + 16*r] = Bm[(size_t)(n0 + ra + 16*r) * ldb + k0 + ka];
        }
        __syncthreads();
#pragma unroll
        for (int kk = 0; kk < 16; kk++) {
            float4 a4 = *(const float4*)&As[kk][ty*4];
            float4 b4 = *(const float4*)&Bs[kk][tx*4];
            float av[4] = {a4.x, a4.y, a4.z, a4.w};
            float bv[4] = {b4.x, b4.y, b4.z, b4.w};
#pragma unroll
            for (int i = 0; i < 4; i++)
#pragma unroll
                for (int j = 0; j < 4; j++)
                    acc[i][j] += av[i] * bv[j];
        }
        __syncthreads();
    }
#pragma unroll
    for (int i = 0; i < 4; i++) {
        float4 o = make_float4(acc[i][0], acc[i][1], acc[i][2], acc[i][3]);
        *(float4*)&C[(size_t)(m0 + ty*4 + i) * ldc + n0 + tx*4] = o;
    }
}

// ---- batched tiled SGEMM, C[m,n] = sum_k A[m,k]*B[k,n]; batch z decomposed as zo*bdiv+zi
__global__ void __launch_bounds__(256) gemm_nn(
    const float* __restrict__ A, const float* __restrict__ Bm, float* __restrict__ C,
    int M, int Nd, int K, int lda, int ldb, int ldc,
    int bdiv, long long sAo, long long sAi, long long sBo, long long sBi,
    long long sCo, long long sCi)
{
    int z = blockIdx.z;
    int zo = z / bdiv, zi = z % bdiv;
    A  += zo * sAo + zi * sAi;
    Bm += zo * sBo + zi * sBi;
    C  += zo * sCo + zi * sCi;

    __shared__ __align__(16) float As[16][68];
    __shared__ __align__(16) float Bs[16][68];
    int t = threadIdx.x;
    int m0 = blockIdx.y * 64, n0 = blockIdx.x * 64;
    int tx = t & 15, ty = t >> 4;
    int ka = t & 15, ra = t >> 4;
    int nb = t & 63, kb = t >> 6;
    float acc[4][4] = {};
    for (int k0 = 0; k0 < K; k0 += 16) {
#pragma unroll
        for (int r = 0; r < 4; r++) {
            As[ka][ra + 16*r] = A[(size_t)(m0 + ra + 16*r) * lda + k0 + ka];
            Bs[kb + 4*r][nb]  = Bm[(size_t)(k0 + kb + 4*r) * ldb + n0 + nb];
        }
        __syncthreads();
#pragma unroll
        for (int kk = 0; kk < 16; kk++) {
            float4 a4 = *(const float4*)&As[kk][ty*4];
            float4 b4 = *(const float4*)&Bs[kk][tx*4];
            float av[4] = {a4.x, a4.y, a4.z, a4.w};
            float bv[4] = {b4.x, b4.y, b4.z, b4.w};
#pragma unroll
            for (int i = 0; i < 4; i++)
#pragma unroll
                for (int j = 0; j < 4; j++)
                    acc[i][j] += av[i] * bv[j];
        }
        __syncthreads();
    }
#pragma unroll
    for (int i = 0; i < 4; i++) {
        float4 o = make_float4(acc[i][0], acc[i][1], acc[i][2], acc[i][3]);
        *(float4*)&C[(size_t)(m0 + ty*4 + i) * ldc + n0 + tx*4] = o;
    }
}

// ---------------- attention scores s_i/s_j ----------------
__global__ void k_sij(const float* __restrict__ attn) {
    int bn = blockIdx.x;                      // b*512 + n
    __shared__ float row[CF];
    for (int i = threadIdx.x; i < CF; i += 256) row[i] = g_hp[(size_t)bn * CF + i];
    __syncthreads();
    int w = threadIdx.x >> 5, lane = threadIdx.x & 31;
    int h = w >> 1, part = w & 1;             // 8 warps: 4 heads x {i,j}
    const float* av = attn + h * (2*CDH) + part * CDH;
    float s = 0.f;
    for (int d = lane; d < CDH; d += 32) s += row[h*CDH + d] * av[d];
#pragma unroll
    for (int o = 16; o; o >>= 1) s += __shfl_xor_sync(0xffffffffu, s, o);
    if (!lane) {
        int b = bn >> 9, n = bn & 511;
        float* dst = part ? g_sj : g_si;
        dst[(b*CH + h)*CN + n] = s;
    }
}

// ---------------- leakyrelu + row softmax -> alpha ----------------
__global__ void k_alpha() {
    int row = blockIdx.x;                     // (b*H + h)*512 + i
    int bh = row >> 9;
    float s_i = g_si[row];
    const float* sjr = g_sj + bh * CN;
    __shared__ float shm[8], shs[8];
    int t = threadIdx.x, lane = t & 31, w = t >> 5;
    float e0 = s_i + sjr[t];       e0 = e0 >= 0.f ? e0 : 0.2f * e0;
    float e1 = s_i + sjr[t + 256]; e1 = e1 >= 0.f ? e1 : 0.2f * e1;
    float m = fmaxf(e0, e1);
#pragma unroll
    for (int o = 16; o; o >>= 1) m = fmaxf(m, __shfl_xor_sync(0xffffffffu, m, o));
    if (!lane) shm[w] = m;
    __syncthreads();
    if (t < 32) {
        float v = (t < 8) ? shm[t] : -INFINITY;
#pragma unroll
        for (int o = 4; o; o >>= 1) v = fmaxf(v, __shfl_xor_sync(0xffffffffu, v, o));
        if (t == 0) shm[0] = v;
    }
    __syncthreads();
    float bm = shm[0];
    float x0 = expf(e0 - bm), x1 = expf(e1 - bm);
    float s = x0 + x1;
#pragma unroll
    for (int o = 16; o; o >>= 1) s += __shfl_xor_sync(0xffffffffu, s, o);
    if (!lane) shs[w] = s;
    __syncthreads();
    if (t < 32) {
        float v = (t < 8) ? shs[t] : 0.f;
#pragma unroll
        for (int o = 4; o; o >>= 1) v += __shfl_xor_sync(0xffffffffu, v, o);
        if (t == 0) shs[0] = v;
    }
    __syncthreads();
    float inv = 1.f / shs[0];
    g_alpha[(size_t)row * CN + t]       = x0 * inv;
    g_alpha[(size_t)row * CN + t + 256] = x1 * inv;
}

// ---------------- edge scores: sum_a relu(pi+pj+b1)*w2 + b2 ----------------
__global__ void __launch_bounds__(256) k_edge(
    const float* __restrict__ b1, const float* __restrict__ w2,
    const float* __restrict__ b2)
{
    int b = blockIdx.z;
    int i0 = blockIdx.y * 16, j0 = blockIdx.x * 16;
    __shared__ float Pi[16][258], Pj[16][258], B1[CAH], W2[CAH];
    int t = threadIdx.y * 16 + threadIdx.x;
    B1[t] = b1[t]; W2[t] = w2[t];
#pragma unroll 4
    for (int r = 0; r < 16; r++) {
        Pi[r][t] = g_pi[(size_t)(b*CN + i0 + r) * CAH + t];
        Pj[r][t] = g_pj[(size_t)(b*CN + j0 + r) * CAH + t];
    }
    __syncthreads();
    int ti = threadIdx.y, tj = threadIdx.x;
    float s = 0.f;
#pragma unroll 4
    for (int a = 0; a < CAH; a++) {
        float v = Pi[ti][a] + Pj[tj][a] + B1[a];
        s += fmaxf(v, 0.f) * W2[a];
    }
    g_edge[(size_t)b * CNN + (i0 + ti) * CN + j0 + tj] = s + b2[0];
}

// ---------------- radix select pass A: hi-16 histogram + max ----------------
__global__ void k_passA() {
    int b = blockIdx.y;
    const float* e = g_edge + (size_t)b * CNN;
    unsigned lm = 0;
    for (int idx = blockIdx.x * blockDim.x + threadIdx.x; idx < CNN;
         idx += gridDim.x * blockDim.x) {
        unsigned key = key_of(e[idx]);
        atomicAdd(&g_hist[(b << 16) + (key >> 16)], 1u);
        lm = max(lm, key);
    }
    __shared__ unsigned sh[8];
    int t = threadIdx.x, lane = t & 31, w = t >> 5;
#pragma unroll
    for (int o = 16; o; o >>= 1) lm = max(lm, __shfl_xor_sync(0xffffffffu, lm, o));
    if (!lane) sh[w] = lm;
    __syncthreads();
    if (t == 0) {
        unsigned v = sh[0];
        for (int q = 1; q < 8; q++) v = max(v, sh[q]);
        atomicMax(&g_maxkey[b], v);
    }
}

__global__ void k_scan1() {
    int b = blockIdx.x;
    unsigned* h = g_hist + (b << 16);
    __shared__ unsigned part[1024];
    int t = threadIdx.x;
    unsigned s = 0;
    for (int i = 0; i < 64; i++) s += h[t*64 + i];
    part[t] = s;
    __syncthreads();
    for (int off = 1; off < 1024; off <<= 1) {
        unsigned v = (t >= off) ? part[t - off] : 0u;
        __syncthreads();
        if (t >= off) part[t] += v;
        __syncthreads();
    }
    unsigned r = RSEL;
    unsigned pre = t ? part[t-1] : 0u;
    if (pre <= r && r < part[t]) {
        unsigned rem = r - pre;
        for (int i = 0; i < 64; i++) {
            unsigned c = h[t*64 + i];
            if (rem < c) { g_selhi[b] = (unsigned)(t*64 + i); g_rank2[b] = rem; break; }
            rem -= c;
        }
    }
    __syncthreads();
    for (int i = t; i < 65536; i += 1024) h[i] = 0;   // re-zero for pass B
}

__global__ void k_passB() {
    int b = blockIdx.y;
    const float* e = g_edge + (size_t)b * CNN;
    unsigned hi = g_selhi[b];
    for (int idx = blockIdx.x * blockDim.x + threadIdx.x; idx < CNN;
         idx += gridDim.x * blockDim.x) {
        unsigned key = key_of(e[idx]);
        if ((key >> 16) == hi) atomicAdd(&g_hist[(b << 16) + (key & 0xFFFFu)], 1u);
    }
}

__global__ void k_scan2() {
    int b = blockIdx.x;
    unsigned* h = g_hist + (b << 16);
    __shared__ unsigned part[1024];
    int t = threadIdx.x;
    unsigned s = 0;
    for (int i = 0; i < 64; i++) s += h[t*64 + i];
    part[t] = s;
    __syncthreads();
    for (int off = 1; off < 1024; off <<= 1) {
        unsigned v = (t >= off) ? part[t - off] : 0u;
        __syncthreads();
        if (t >= off) part[t] += v;
        __syncthreads();
    }
    unsigned r = g_rank2[b];
    unsigned pre = t ? part[t-1] : 0u;
    if (pre <= r && r < part[t]) {
        unsigned rem = r - pre;
        for (int i = 0; i < 64; i++) {
            unsigned c = h[t*64 + i];
            if (rem < c) {
                unsigned key = (g_selhi[b] << 16) | (unsigned)(t*64 + i);
                g_thr[b] = key_inv(key);
                break;
            }
            rem -= c;
        }
    }
}

// ---------------- masked exp + partial sums ----------------
__global__ void k_maskexp() {
    int b = blockIdx.y;
    const float* e = g_edge + (size_t)b * CNN;
    float* cm = g_cm + (size_t)b * CNN;
    float zmax = key_inv(g_maxkey[b]);
    float th = g_thr[b];
    float ls = 0.f;
    for (int idx = blockIdx.x * blockDim.x + threadIdx.x; idx < CNN;
         idx += gridDim.x * blockDim.x) {
        float z = e[idx];
        float v = 0.f;
        if (z >= th) v = expf((z - zmax) * 2.0f);   // 1/TEMP = 2
        cm[idx] = v;
        ls += v;
    }
    __shared__ float sh[8];
    int t = threadIdx.x, lane = t & 31, w = t >> 5;
#pragma unroll
    for (int o = 16; o; o >>= 1) ls += __shfl_xor_sync(0xffffffffu, ls, o);
    if (!lane) sh[w] = ls;
    __syncthreads();
    if (t == 0) {
        float v = sh[0];
        for (int q = 1; q < 8; q++) v += sh[q];
        atomicAdd(&g_msum[b], v);
    }
}

__global__ void k_norm() {
    int b = blockIdx.y;
    float inv = 1.f / g_msum[b];
    float* cm = g_cm + (size_t)b * CNN;
    for (int idx = blockIdx.x * blockDim.x + threadIdx.x; idx < CNN;
         idx += gridDim.x * blockDim.x)
        cm[idx] *= inv;
}

// ---------------- batch norm ----------------
__global__ void k_bnstats(const float* __restrict__ h, int C, float* sum, float* sq) {
    int row0 = blockIdx.x * 32;
    int c = threadIdx.x;
    float s = 0.f, q = 0.f;
    for (int r = 0; r < 32; r++) {
        float v = h[(size_t)(row0 + r) * C + c];
        s += v; q += v * v;
    }
    atomicAdd(&sum[c], s);
    atomicAdd(&sq[c], q);
}

__global__ void k_bnfinal(const float* sum, const float* sq,
                          const float* __restrict__ g, const float* __restrict__ bt,
                          float* scale, float* shift) {
    int c = threadIdx.x;
    const float invn = 1.f / (CB * CN);
    float mean = sum[c] * invn;
    float var = sq[c] * invn - mean * mean;
    float sc = g[c] * rsqrtf(var + 1e-5f);
    scale[c] = sc;
    shift[c] = bt[c] - mean * sc;
}

__global__ void k_bnrelu(float* h, int Cmask, int total, const float* scale, const float* shift) {
    for (int idx = blockIdx.x * blockDim.x + threadIdx.x; idx < total;
         idx += gridDim.x * blockDim.x) {
        int c = idx & Cmask;
        h[idx] = fmaxf(h[idx] * scale[c] + shift[c], 0.f);
    }
}

// ---------------- BN2-apply + relu + mean over N ----------------
__global__ void k_feat() {
    int b = blockIdx.x;
    int c = threadIdx.x;   // 128
    float sc = g_sc2[c], sh = g_sh2[c];
    float s = 0.f;
    for (int n = 0; n < CN; n++) {
        float v = g_h4[(size_t)(b*CN + n) * COUT + c] * sc + sh;
        s += fmaxf(v, 0.f);
    }
    g_feat[b*COUT + c] = s * (1.f / CN);
}

// ---------------- classifier ----------------
__global__ void k_cls(const float* __restrict__ cw, const float* __restrict__ cb,
                      float* __restrict__ out) {
    int w = threadIdx.x >> 5, lane = threadIdx.x & 31;
    if (w < CB * CNCLS) {
        int b = w / CNCLS, c = w % CNCLS;
        float s = 0.f;
        for (int f = lane; f < COUT; f += 32)
            s += g_feat[b*COUT + f] * cw[c*COUT + f];
#pragma unroll
        for (int o = 16; o; o >>= 1) s += __shfl_xor_sync(0xffffffffu, s, o);
        if (!lane) out[b*CNCLS + c] = s + cb[c];
    }
}

// ---------------- host launch ----------------
extern "C" void kernel_launch(void* const* d_in, const int* in_sizes, int n_in,
                              void* d_out, int out_size) {
    (void)in_sizes; (void)n_in; (void)out_size;
    const float* x    = (const float*)d_in[0];
    const float* Wg   = (const float*)d_in[1];
    const float* attn = (const float*)d_in[2];
    const float* W1   = (const float*)d_in[3];
    const float* b1   = (const float*)d_in[4];
    const float* w2   = (const float*)d_in[5];
    const float* b2   = (const float*)d_in[6];
    const float* gc1w = (const float*)d_in[7];
    /* gc1_b (8) cancels in BN */
    const float* bn1g = (const float*)d_in[9];
    const float* bn1b = (const float*)d_in[10];
    const float* gc2w = (const float*)d_in[11];
    /* gc2_b (12) cancels in BN */
    const float* bn2g = (const float*)d_in[13];
    const float* bn2b = (const float*)d_in[14];
    const float* clsw = (const float*)d_in[15];
    const float* clsb = (const float*)d_in[16];
    float* out = (float*)d_out;

    float *hp, *nf, *pi, *pj, *cm, *h1, *h2, *h3, *h4;
    float *bs1, *bq1, *sc1, *sh1, *bs2, *bq2, *sc2, *sh2;
    float *al;
    cudaGetSymbolAddress((void**)&hp,  g_hp);
    cudaGetSymbolAddress((void**)&al,  g_alpha);
    cudaGetSymbolAddress((void**)&nf,  g_nf);
    cudaGetSymbolAddress((void**)&pi,  g_pi);
    cudaGetSymbolAddress((void**)&pj,  g_pj);
    cudaGetSymbolAddress((void**)&cm,  g_cm);
    cudaGetSymbolAddress((void**)&h1,  g_h1);
    cudaGetSymbolAddress((void**)&h2,  g_h2);
    cudaGetSymbolAddress((void**)&h3,  g_h3);
    cudaGetSymbolAddress((void**)&h4,  g_h4);
    cudaGetSymbolAddress((void**)&bs1, g_bs1);
    cudaGetSymbolAddress((void**)&bq1, g_bq1);
    cudaGetSymbolAddress((void**)&sc1, g_sc1);
    cudaGetSymbolAddress((void**)&sh1, g_sh1);
    cudaGetSymbolAddress((void**)&bs2, g_bs2);
    cudaGetSymbolAddress((void**)&bq2, g_bq2);
    cudaGetSymbolAddress((void**)&sc2, g_sc2);
    cudaGetSymbolAddress((void**)&sh2, g_sh2);

    k_zero<<<512, 256>>>();

    // hp = x @ Wg^T     (1024 x 1024 x 1024)
    gemm_nt<<<dim3(CF/64, (CB*CN)/64), 256>>>(x, Wg, hp, CB*CN, CF, CF, CF, CF, CF);

    k_sij<<<CB*CN, 256>>>(attn);
    k_alpha<<<CB*CH*CN, 256>>>();

    // node_feats: per (b,h)  alpha(512x512) @ hp_bh(512x256, ld 1024) -> nf (ld 1024)
    gemm_nn<<<dim3(CDH/64, CN/64, CB*CH), 256>>>(
        al, hp, nf, CN, CDH, CN, CN, CF, CF,
        CH, (long long)CH*CNN, (long long)CNN,
        (long long)CN*CF, (long long)CDH,
        (long long)CN*CF, (long long)CDH);

    // pi / pj = nf @ W1i^T / W1j^T
    gemm_nt<<<dim3(CAH/64, (CB*CN)/64), 256>>>(nf, W1,      pi, CB*CN, CAH, CF, CF, 2*CF, CAH);
    gemm_nt<<<dim3(CAH/64, (CB*CN)/64), 256>>>(nf, W1 + CF, pj, CB*CN, CAH, CF, CF, 2*CF, CAH);

    k_edge<<<dim3(CN/16, CN/16, CB), dim3(16, 16)>>>(b1, w2, b2);

    // exact top-k threshold via 2-pass radix select, then masked exp + normalize
    k_passA<<<dim3(128, CB), 256>>>();
    k_scan1<<<CB, 1024>>>();
    k_passB<<<dim3(128, CB), 256>>>();
    k_scan2<<<CB, 1024>>>();
    k_maskexp<<<dim3(128, CB), 256>>>();
    k_norm<<<dim3(128, CB), 256>>>();

    // h1 = cm @ nf    (per batch 512x1024x512)
    gemm_nn<<<dim3(CF/64, CN/64, CB), 256>>>(
        cm, nf, h1, CN, CF, CN, CN, CF, CF,
        1, (long long)CNN, 0, (long long)CN*CF, 0, (long long)CN*CF, 0);

    // h2 = h1 @ gc1_w^T   (1024 x 512 x 1024)   [gc1_b cancels in BN]
    gemm_nt<<<dim3(CHID/64, (CB*CN)/64), 256>>>(h1, gc1w, h2, CB*CN, CHID, CF, CF, CF, CHID);

    k_bnstats<<<(CB*CN)/32, CHID>>>(h2, CHID, bs1, bq1);
    k_bnfinal<<<1, CHID>>>(bs1, bq1, bn1g, bn1b, sc1, sh1);
    k_bnrelu<<<256, 256>>>(h2, CHID-1, CB*CN*CHID, sc1, sh1);

    // h3 = cm @ h2    (per batch 512x512x512)
    gemm_nn<<<dim3(CHID/64, CN/64, CB), 256>>>(
        cm, h2, h3, CN, CHID, CN, CN, CHID, CHID,
        1, (long long)CNN, 0, (long long)CN*CHID, 0, (long long)CN*CHID, 0);

    // h4 = h3 @ gc2_w^T   (1024 x 128 x 512)    [gc2_b cancels in BN]
    gemm_nt<<<dim3(COUT/64, (CB*CN)/64), 256>>>(h3, gc2w, h4, CB*CN, COUT, CHID, CHID, CHID, COUT);

    k_bnstats<<<(CB*CN)/32, COUT>>>(h4, COUT, bs2, bq2);
    k_bnfinal<<<1, COUT>>>(bs2, bq2, bn2g, bn2b, sc2, sh2);

    k_feat<<<CB, COUT>>>();
    k_cls<<<1, 640>>>(clsw, clsb, out);
}

// round 3
// speedup vs baseline: 1.1200x; 1.1200x over previous
#include <cuda_runtime.h>
#include <math.h>

#define CB 2
#define CN 512
#define CF 1024
#define CH 4
#define CDH 256
#define CAH 256
#define CHID 512
#define COUT 128
#define CNCLS 10
#define CNN (CN*CN)
#define RSEL 52429u   /* NN - int(0.8*NN) = 262144 - 209715 */

// ---------------- scratch (static device memory; no allocations) ----------------
__device__ float g_hp[CB*CN*CF];
__device__ float g_si[CB*CH*CN];
__device__ float g_sj[CB*CH*CN];
__device__ float g_alpha[CB*CH*CN*CN];
__device__ float g_nf[CB*CN*CF];
__device__ float g_pij[2*CB*CN*CAH];
__device__ float g_edge[CB*CNN];
__device__ float g_cm[CB*CNN];
__device__ float g_h1[CB*CN*CF];
__device__ float g_h2[CB*CN*CHID];
__device__ float g_h3[CB*CN*CHID];
__device__ float g_h4[CB*CN*COUT];
__device__ float g_feat[CB*COUT];
__device__ unsigned g_hist[CB*65536];
__device__ unsigned g_selhi[CB];
__device__ unsigned g_rank2[CB];
__device__ unsigned g_maxkey[CB];
__device__ float g_thr[CB];
__device__ float g_msum[CB];
__device__ float g_bs1[CHID], g_bq1[CHID], g_sc1[CHID], g_sh1[CHID];
__device__ float g_bs2[COUT], g_bq2[COUT], g_sc2[COUT], g_sh2[COUT];

// ---------------- helpers ----------------
__device__ __forceinline__ unsigned key_of(float x) {
    unsigned u = __float_as_uint(x);
    return (u & 0x80000000u) ? ~u : (u | 0x80000000u);
}
__device__ __forceinline__ float key_inv(unsigned key) {
    unsigned u = (key & 0x80000000u) ? (key ^ 0x80000000u) : ~key;
    return __uint_as_float(u);
}
__device__ __forceinline__ unsigned long long pk2(float lo, float hi) {
    unsigned long long r;
    asm("mov.b64 %0, {%1, %2};" : "=l"(r) : "f"(lo), "f"(hi));
    return r;
}
__device__ __forceinline__ void fma2(unsigned long long& d, unsigned long long a, unsigned long long b) {
    asm("fma.rn.f32x2 %0, %1, %2, %0;" : "+l"(d) : "l"(a), "l"(b));
}
__device__ __forceinline__ float2 up2(unsigned long long v) {
    float2 f;
    asm("mov.b64 {%0, %1}, %2;" : "=f"(f.x), "=f"(f.y) : "l"(v));
    return f;
}

// ---------------- zero scratch (must run every launch; graph replays) ----------------
__global__ void k_zero() {
    int i = blockIdx.x * 256 + threadIdx.x;       // grid = 512 blocks -> 131072 threads
    g_hist[i] = 0;
    if (i < CHID) { g_bs1[i] = 0.f; g_bq1[i] = 0.f; }
    if (i < COUT) { g_bs2[i] = 0.f; g_bq2[i] = 0.f; }
    if (i < CB)   { g_msum[i] = 0.f; g_maxkey[i] = 0u; }
}

// ================= f32x2 SGEMM: tile M64 x N128, 128 threads, 8x8 microtile =========
// C[m,n] = sum_k A[m,k]*B'[k,n].
// BT=true : B given as [n][k] row-major (ld=ldb), i.e. C = A @ B^T
// BT=false: B given as [k][n] row-major (ld=ldb)
// batch z: zo=z/bdiv, zi=z%bdiv; pointers offset by zo*s?o + zi*s?i
template<bool BT>
__global__ void __launch_bounds__(128) gemm_t(
    const float* __restrict__ A, const float* __restrict__ Bm, float* __restrict__ C,
    int K, int lda, int ldb, int ldc,
    int bdiv, long long sAo, long long sAi, long long sBo, long long sBi,
    long long sCo, long long sCi)
{
    int z = blockIdx.z;
    int zo = z / bdiv, zi = z - zo * bdiv;
    A  += zo * sAo + zi * sAi;
    Bm += zo * sBo + zi * sBi;
    C  += zo * sCo + zi * sCi;

    __shared__ __align__(16) float As[16][68];
    __shared__ __align__(16) float Bs[16][128];

    int t = threadIdx.x;
    int tx = t & 15, ty = t >> 4;
    int m0 = blockIdx.y * 64, n0 = blockIdx.x * 128;

    // A load: thread handles row m0 + (t>>1), k-range (t&1)*8 .. +8 (2 float4)
    int am = t >> 1;
    int ak = (t & 1) * 8;
    const float* Ap = A + (size_t)(m0 + am) * lda + ak;

    // B load pointers
    const float* Bp0;
    const float* Bq[4];
    int bnc[4];
    if (BT) {
        Bp0 = Bm + (size_t)(n0 + t) * ldb;         // 4 float4 along k
    } else {
        #pragma unroll
        for (int c = 0; c < 4; c++) {
            int q = t + 128 * c;
            int kr = q >> 5;                        // 0..15
            bnc[c] = (q & 31) * 4;
            Bq[c] = Bm + (size_t)kr * ldb + n0 + bnc[c];
        }
        Bp0 = 0;
    }

    float4 ra[2], rb[4];
    ra[0] = *(const float4*)(Ap);
    ra[1] = *(const float4*)(Ap + 4);
    if (BT) {
        #pragma unroll
        for (int c = 0; c < 4; c++) rb[c] = *(const float4*)(Bp0 + c * 4);
    } else {
        #pragma unroll
        for (int c = 0; c < 4; c++) rb[c] = *(const float4*)(Bq[c]);
    }

    unsigned long long acc[8][4];
    #pragma unroll
    for (int i = 0; i < 8; i++)
        #pragma unroll
        for (int j = 0; j < 4; j++) acc[i][j] = 0ull;

    int k0 = 0;
    for (;;) {
        // stage regs -> smem
        #pragma unroll
        for (int c = 0; c < 2; c++) {
            float v[4] = {ra[c].x, ra[c].y, ra[c].z, ra[c].w};
            #pragma unroll
            for (int e = 0; e < 4; e++) As[ak + c * 4 + e][am] = v[e];
        }
        if (BT) {
            #pragma unroll
            for (int c = 0; c < 4; c++) {
                float v[4] = {rb[c].x, rb[c].y, rb[c].z, rb[c].w};
                #pragma unroll
                for (int e = 0; e < 4; e++) Bs[c * 4 + e][t] = v[e];
            }
        } else {
            #pragma unroll
            for (int c = 0; c < 4; c++) {
                int q = t + 128 * c;
                *(float4*)&Bs[q >> 5][bnc[c]] = rb[c];
            }
        }
        __syncthreads();

        k0 += 16;
        bool more = k0 < K;
        if (more) {
            ra[0] = *(const float4*)(Ap + k0);
            ra[1] = *(const float4*)(Ap + k0 + 4);
            if (BT) {
                #pragma unroll
                for (int c = 0; c < 4; c++) rb[c] = *(const float4*)(Bp0 + k0 + c * 4);
            } else {
                #pragma unroll
                for (int c = 0; c < 4; c++) {
                    Bq[c] += (size_t)16 * ldb;
                    rb[c] = *(const float4*)(Bq[c]);
                }
            }
        }

        #pragma unroll
        for (int kk = 0; kk < 16; kk++) {
            float4 a0 = *(const float4*)&As[kk][ty * 4];
            float4 a1 = *(const float4*)&As[kk][32 + ty * 4];
            ulonglong2 b0 = *(const ulonglong2*)&Bs[kk][tx * 4];
            ulonglong2 b1 = *(const ulonglong2*)&Bs[kk][64 + tx * 4];
            unsigned long long ap[8] = {
                pk2(a0.x, a0.x), pk2(a0.y, a0.y), pk2(a0.z, a0.z), pk2(a0.w, a0.w),
                pk2(a1.x, a1.x), pk2(a1.y, a1.y), pk2(a1.z, a1.z), pk2(a1.w, a1.w)};
            unsigned long long bp[4] = {b0.x, b0.y, b1.x, b1.y};
            #pragma unroll
            for (int i = 0; i < 8; i++)
                #pragma unroll
                for (int j = 0; j < 4; j++)
                    fma2(acc[i][j], ap[i], bp[j]);
        }
        __syncthreads();
        if (!more) break;
    }

    // epilogue
    #pragma unroll
    for (int g = 0; g < 2; g++)
        #pragma unroll
        for (int r = 0; r < 4; r++) {
            int i = g * 4 + r;
            int row = m0 + g * 32 + ty * 4 + r;
            float2 x0 = up2(acc[i][0]), x1 = up2(acc[i][1]);
            float2 x2 = up2(acc[i][2]), x3 = up2(acc[i][3]);
            *(float4*)&C[(size_t)row * ldc + n0 + tx * 4] =
                make_float4(x0.x, x0.y, x1.x, x1.y);
            *(float4*)&C[(size_t)row * ldc + n0 + 64 + tx * 4] =
                make_float4(x2.x, x2.y, x3.x, x3.y);
        }
}

// ---------------- attention scores s_i/s_j ----------------
__global__ void k_sij(const float* __restrict__ attn) {
    int bn = blockIdx.x;                      // b*512 + n
    __shared__ float row[CF];
    for (int i = threadIdx.x; i < CF; i += 256) row[i] = g_hp[(size_t)bn * CF + i];
    __syncthreads();
    int w = threadIdx.x >> 5, lane = threadIdx.x & 31;
    int h = w >> 1, part = w & 1;             // 8 warps: 4 heads x {i,j}
    const float* av = attn + h * (2*CDH) + part * CDH;
    float s = 0.f;
    for (int d = lane; d < CDH; d += 32) s += row[h*CDH + d] * av[d];
#pragma unroll
    for (int o = 16; o; o >>= 1) s += __shfl_xor_sync(0xffffffffu, s, o);
    if (!lane) {
        int b = bn >> 9, n = bn & 511;
        float* dst = part ? g_sj : g_si;
        dst[(b*CH + h)*CN + n] = s;
    }
}

// ---------------- leakyrelu + row softmax -> alpha ----------------
__global__ void k_alpha() {
    int row = blockIdx.x;                     // (b*H + h)*512 + i
    int bh = row >> 9;
    float s_i = g_si[row];
    const float* sjr = g_sj + bh * CN;
    __shared__ float shm[8], shs[8];
    int t = threadIdx.x, lane = t & 31, w = t >> 5;
    float e0 = s_i + sjr[t];       e0 = e0 >= 0.f ? e0 : 0.2f * e0;
    float e1 = s_i + sjr[t + 256]; e1 = e1 >= 0.f ? e1 : 0.2f * e1;
    float m = fmaxf(e0, e1);
#pragma unroll
    for (int o = 16; o; o >>= 1) m = fmaxf(m, __shfl_xor_sync(0xffffffffu, m, o));
    if (!lane) shm[w] = m;
    __syncthreads();
    if (t < 32) {
        float v = (t < 8) ? shm[t] : -INFINITY;
#pragma unroll
        for (int o = 4; o; o >>= 1) v = fmaxf(v, __shfl_xor_sync(0xffffffffu, v, o));
        if (t == 0) shm[0] = v;
    }
    __syncthreads();
    float bm = shm[0];
    float x0 = expf(e0 - bm), x1 = expf(e1 - bm);
    float s = x0 + x1;
#pragma unroll
    for (int o = 16; o; o >>= 1) s += __shfl_xor_sync(0xffffffffu, s, o);
    if (!lane) shs[w] = s;
    __syncthreads();
    if (t < 32) {
        float v = (t < 8) ? shs[t] : 0.f;
#pragma unroll
        for (int o = 4; o; o >>= 1) v += __shfl_xor_sync(0xffffffffu, v, o);
        if (t == 0) shs[0] = v;
    }
    __syncthreads();
    float inv = 1.f / shs[0];
    g_alpha[(size_t)row * CN + t]       = x0 * inv;
    g_alpha[(size_t)row * CN + t + 256] = x1 * inv;
}

// ------- edge scores: sum_a relu(pi+pj+b1)*w2 + b2; 32x32 tile, 2x2 microtile -------
__global__ void __launch_bounds__(256) k_edge(
    const float* __restrict__ b1, const float* __restrict__ w2,
    const float* __restrict__ b2)
{
    int b = blockIdx.z;
    int i0 = blockIdx.y * 32, j0 = blockIdx.x * 32;
    __shared__ __align__(16) float Pi[32][132], Pj[32][132];
    __shared__ float B1s[128], W2s[128];
    const float* pi = g_pij;
    const float* pj = g_pij + (size_t)CB*CN*CAH;
    int t = threadIdx.x;
    int ti = t >> 4, tj = t & 15;
    float acc[2][2] = {};
    for (int a0 = 0; a0 < CAH; a0 += 128) {
        if (t < 128) { B1s[t] = b1[a0 + t]; W2s[t] = w2[a0 + t]; }
        #pragma unroll
        for (int c = 0; c < 4; c++) {
            int q = t + 256 * c;            // 0..1023 over 32 rows x 32 float4
            int r = q >> 5, nc = (q & 31) * 4;
            *(float4*)&Pi[r][nc] = *(const float4*)&pi[(size_t)(b*CN + i0 + r) * CAH + a0 + nc];
            *(float4*)&Pj[r][nc] = *(const float4*)&pj[(size_t)(b*CN + j0 + r) * CAH + a0 + nc];
        }
        __syncthreads();
        #pragma unroll 8
        for (int a = 0; a < 128; a += 4) {
            float4 u0 = *(const float4*)&Pi[2*ti][a];
            float4 u1 = *(const float4*)&Pi[2*ti + 1][a];
            float4 v0 = *(const float4*)&Pj[2*tj][a];
            float4 v1 = *(const float4*)&Pj[2*tj + 1][a];
            float4 bb = *(const float4*)&B1s[a];
            float4 ww = *(const float4*)&W2s[a];
            #define EDGE_E(ue, ve, be, we) { \
                float p00 = ue.x + ve.x + be; float p01 = ue.x + ve.y + be; \
                float p10 = ue.y + ve.x + be; float p11 = ue.y + ve.y + be; \
                acc[0][0] += fmaxf(p00, 0.f) * we; \
                acc[0][1] += fmaxf(p01, 0.f) * we; \
                acc[1][0] += fmaxf(p10, 0.f) * we; \
                acc[1][1] += fmaxf(p11, 0.f) * we; }
            { float2 uu = make_float2(u0.x, u1.x), vv = make_float2(v0.x, v1.x); EDGE_E(uu, vv, bb.x, ww.x); }
            { float2 uu = make_float2(u0.y, u1.y), vv = make_float2(v0.y, v1.y); EDGE_E(uu, vv, bb.y, ww.y); }
            { float2 uu = make_float2(u0.z, u1.z), vv = make_float2(v0.z, v1.z); EDGE_E(uu, vv, bb.z, ww.z); }
            { float2 uu = make_float2(u0.w, u1.w), vv = make_float2(v0.w, v1.w); EDGE_E(uu, vv, bb.w, ww.w); }
            #undef EDGE_E
        }
        __syncthreads();
    }
    float bias = b2[0];
    #pragma unroll
    for (int r = 0; r < 2; r++) {
        float2 o = make_float2(acc[r][0] + bias, acc[r][1] + bias);
        *(float2*)&g_edge[(size_t)b * CNN + (i0 + 2*ti + r) * CN + j0 + 2*tj] = o;
    }
}

// ---------------- radix select pass A: hi-16 histogram + max ----------------
__global__ void k_passA() {
    int b = blockIdx.y;
    const float* e = g_edge + (size_t)b * CNN;
    unsigned lm = 0;
    for (int idx = blockIdx.x * blockDim.x + threadIdx.x; idx < CNN;
         idx += gridDim.x * blockDim.x) {
        unsigned key = key_of(e[idx]);
        atomicAdd(&g_hist[(b << 16) + (key >> 16)], 1u);
        lm = max(lm, key);
    }
    __shared__ unsigned sh[8];
    int t = threadIdx.x, lane = t & 31, w = t >> 5;
#pragma unroll
    for (int o = 16; o; o >>= 1) lm = max(lm, __shfl_xor_sync(0xffffffffu, lm, o));
    if (!lane) sh[w] = lm;
    __syncthreads();
    if (t == 0) {
        unsigned v = sh[0];
        for (int q = 1; q < 8; q++) v = max(v, sh[q]);
        atomicMax(&g_maxkey[b], v);
    }
}

__global__ void k_scan1() {
    int b = blockIdx.x;
    unsigned* h = g_hist + (b << 16);
    __shared__ unsigned part[1024];
    int t = threadIdx.x;
    unsigned s = 0;
    for (int i = 0; i < 64; i++) s += h[t*64 + i];
    part[t] = s;
    __syncthreads();
    for (int off = 1; off < 1024; off <<= 1) {
        unsigned v = (t >= off) ? part[t - off] : 0u;
        __syncthreads();
        if (t >= off) part[t] += v;
        __syncthreads();
    }
    unsigned r = RSEL;
    unsigned pre = t ? part[t-1] : 0u;
    if (pre <= r && r < part[t]) {
        unsigned rem = r - pre;
        for (int i = 0; i < 64; i++) {
            unsigned c = h[t*64 + i];
            if (rem < c) { g_selhi[b] = (unsigned)(t*64 + i); g_rank2[b] = rem; break; }
            rem -= c;
        }
    }
    __syncthreads();
    for (int i = t; i < 65536; i += 1024) h[i] = 0;   // re-zero for pass B
}

__global__ void k_passB() {
    int b = blockIdx.y;
    const float* e = g_edge + (size_t)b * CNN;
    unsigned hi = g_selhi[b];
    for (int idx = blockIdx.x * blockDim.x + threadIdx.x; idx < CNN;
         idx += gridDim.x * blockDim.x) {
        unsigned key = key_of(e[idx]);
        if ((key >> 16) == hi) atomicAdd(&g_hist[(b << 16) + (key & 0xFFFFu)], 1u);
    }
}

__global__ void k_scan2() {
    int b = blockIdx.x;
    unsigned* h = g_hist + (b << 16);
    __shared__ unsigned part[1024];
    int t = threadIdx.x;
    unsigned s = 0;
    for (int i = 0; i < 64; i++) s += h[t*64 + i];
    part[t] = s;
    __syncthreads();
    for (int off = 1; off < 1024; off <<= 1) {
        unsigned v = (t >= off) ? part[t - off] : 0u;
        __syncthreads();
        if (t >= off) part[t] += v;
        __syncthreads();
    }
    unsigned r = g_rank2[b];
    unsigned pre = t ? part[t-1] : 0u;
    if (pre <= r && r < part[t]) {
        unsigned rem = r - pre;
        for (int i = 0; i < 64; i++) {
            unsigned c = h[t*64 + i];
            if (rem < c) {
                unsigned key = (g_selhi[b] << 16) | (unsigned)(t*64 + i);
                g_thr[b] = key_inv(key);
                break;
            }
            rem -= c;
        }
    }
}

// ---------------- masked exp + partial sums ----------------
__global__ void k_maskexp() {
    int b = blockIdx.y;
    const float* e = g_edge + (size_t)b * CNN;
    float* cm = g_cm + (size_t)b * CNN;
    float zmax = key_inv(g_maxkey[b]);
    float th = g_thr[b];
    float ls = 0.f;
    for (int idx = blockIdx.x * blockDim.x + threadIdx.x; idx < CNN;
         idx += gridDim.x * blockDim.x) {
        float z = e[idx];
        float v = 0.f;
        if (z >= th) v = expf((z - zmax) * 2.0f);   // 1/TEMP = 2
        cm[idx] = v;
        ls += v;
    }
    __shared__ float sh[8];
    int t = threadIdx.x, lane = t & 31, w = t >> 5;
#pragma unroll
    for (int o = 16; o; o >>= 1) ls += __shfl_xor_sync(0xffffffffu, ls, o);
    if (!lane) sh[w] = ls;
    __syncthreads();
    if (t == 0) {
        float v = sh[0];
        for (int q = 1; q < 8; q++) v += sh[q];
        atomicAdd(&g_msum[b], v);
    }
}

__global__ void k_norm() {
    int b = blockIdx.y;
    float inv = 1.f / g_msum[b];
    float* cm = g_cm + (size_t)b * CNN;
    for (int idx = blockIdx.x * blockDim.x + threadIdx.x; idx < CNN;
         idx += gridDim.x * blockDim.x)
        cm[idx] *= inv;
}

// ---------------- batch norm ----------------
__global__ void k_bnstats(const float* __restrict__ h, int C, float* sum, float* sq) {
    int row0 = blockIdx.x * 32;
    int c = threadIdx.x;
    float s = 0.f, q = 0.f;
    for (int r = 0; r < 32; r++) {
        float v = h[(size_t)(row0 + r) * C + c];
        s += v; q += v * v;
    }
    atomicAdd(&sum[c], s);
    atomicAdd(&sq[c], q);
}

__global__ void k_bnfinal(const float* sum, const float* sq,
                          const float* __restrict__ g, const float* __restrict__ bt,
                          float* scale, float* shift) {
    int c = threadIdx.x;
    const float invn = 1.f / (CB * CN);
    float mean = sum[c] * invn;
    float var = sq[c] * invn - mean * mean;
    float sc = g[c] * rsqrtf(var + 1e-5f);
    scale[c] = sc;
    shift[c] = bt[c] - mean * sc;
}

__global__ void k_bnrelu(float* h, int Cmask, int total, const float* scale, const float* shift) {
    for (int idx = blockIdx.x * blockDim.x + threadIdx.x; idx < total;
         idx += gridDim.x * blockDim.x) {
        int c = idx & Cmask;
        h[idx] = fmaxf(h[idx] * scale[c] + shift[c], 0.f);
    }
}

// ---------------- BN2-apply + relu + mean over N ----------------
__global__ void k_feat() {
    int b = blockIdx.x;
    int c = threadIdx.x;   // 128
    float sc = g_sc2[c], sh = g_sh2[c];
    float s = 0.f;
    for (int n = 0; n < CN; n++) {
        float v = g_h4[(size_t)(b*CN + n) * COUT + c] * sc + sh;
        s += fmaxf(v, 0.f);
    }
    g_feat[b*COUT + c] = s * (1.f / CN);
}

// ---------------- classifier ----------------
__global__ void k_cls(const float* __restrict__ cw, const float* __restrict__ cb,
                      float* __restrict__ out) {
    int w = threadIdx.x >> 5, lane = threadIdx.x & 31;
    if (w < CB * CNCLS) {
        int b = w / CNCLS, c = w % CNCLS;
        float s = 0.f;
        for (int f = lane; f < COUT; f += 32)
            s += g_feat[b*COUT + f] * cw[c*COUT + f];
#pragma unroll
        for (int o = 16; o; o >>= 1) s += __shfl_xor_sync(0xffffffffu, s, o);
        if (!lane) out[b*CNCLS + c] = s + cb[c];
    }
}

// ---------------- host launch ----------------
extern "C" void kernel_launch(void* const* d_in, const int* in_sizes, int n_in,
                              void* d_out, int out_size) {
    (void)in_sizes; (void)n_in; (void)out_size;
    const float* x    = (const float*)d_in[0];
    const float* Wg   = (const float*)d_in[1];
    const float* attn = (const float*)d_in[2];
    const float* W1   = (const float*)d_in[3];
    const float* b1   = (const float*)d_in[4];
    const float* w2   = (const float*)d_in[5];
    const float* b2   = (const float*)d_in[6];
    const float* gc1w = (const float*)d_in[7];
    /* gc1_b (8) cancels in BN */
    const float* bn1g = (const float*)d_in[9];
    const float* bn1b = (const float*)d_in[10];
    const float* gc2w = (const float*)d_in[11];
    /* gc2_b (12) cancels in BN */
    const float* bn2g = (const float*)d_in[13];
    const float* bn2b = (const float*)d_in[14];
    const float* clsw = (const float*)d_in[15];
    const float* clsb = (const float*)d_in[16];
    float* out = (float*)d_out;

    float *hp, *nf, *pij, *cm, *h1, *h2, *h3, *h4;
    float *bs1, *bq1, *sc1, *sh1, *bs2, *bq2, *sc2, *sh2;
    float *al;
    cudaGetSymbolAddress((void**)&hp,  g_hp);
    cudaGetSymbolAddress((void**)&al,  g_alpha);
    cudaGetSymbolAddress((void**)&nf,  g_nf);
    cudaGetSymbolAddress((void**)&pij, g_pij);
    cudaGetSymbolAddress((void**)&cm,  g_cm);
    cudaGetSymbolAddress((void**)&h1,  g_h1);
    cudaGetSymbolAddress((void**)&h2,  g_h2);
    cudaGetSymbolAddress((void**)&h3,  g_h3);
    cudaGetSymbolAddress((void**)&h4,  g_h4);
    cudaGetSymbolAddress((void**)&bs1, g_bs1);
    cudaGetSymbolAddress((void**)&bq1, g_bq1);
    cudaGetSymbolAddress((void**)&sc1, g_sc1);
    cudaGetSymbolAddress((void**)&sh1, g_sh1);
    cudaGetSymbolAddress((void**)&bs2, g_bs2);
    cudaGetSymbolAddress((void**)&bq2, g_bq2);
    cudaGetSymbolAddress((void**)&sc2, g_sc2);
    cudaGetSymbolAddress((void**)&sh2, g_sh2);

    k_zero<<<512, 256>>>();

    // hp = x @ Wg^T     (1024 x 1024 x 1024)
    gemm_t<true><<<dim3(CF/128, (CB*CN)/64, 1), 128>>>(
        x, Wg, hp, CF, CF, CF, CF, 1, 0,0, 0,0, 0,0);

    k_sij<<<CB*CN, 256>>>(attn);
    k_alpha<<<CB*CH*CN, 256>>>();

    // node_feats: per (b,h)  alpha(512x512) @ hp_bh(512x256, ld 1024) -> nf (ld 1024)
    gemm_t<false><<<dim3(CDH/128, CN/64, CB*CH), 128>>>(
        al, hp, nf, CN, CN, CF, CF,
        CH, (long long)CH*CNN, (long long)CNN,
        (long long)CN*CF, (long long)CDH,
        (long long)CN*CF, (long long)CDH);

    // pi / pj = nf @ W1i^T / W1j^T   (z selects half of W1 and output block)
    gemm_t<true><<<dim3(CAH/128, (CB*CN)/64, 2), 128>>>(
        nf, W1, pij, CF, CF, 2*CF, CAH,
        1, 0, 0, (long long)CF, 0, (long long)CB*CN*CAH, 0);

    k_edge<<<dim3(CN/32, CN/32, CB), 256>>>(b1, w2, b2);

    // exact top-k threshold via 2-pass radix select, then masked exp + normalize
    k_passA<<<dim3(128, CB), 256>>>();
    k_scan1<<<CB, 1024>>>();
    k_passB<<<dim3(128, CB), 256>>>();
    k_scan2<<<CB, 1024>>>();
    k_maskexp<<<dim3(128, CB), 256>>>();
    k_norm<<<dim3(128, CB), 256>>>();

    // h1 = cm @ nf    (per batch 512x1024x512)
    gemm_t<false><<<dim3(CF/128, CN/64, CB), 128>>>(
        cm, nf, h1, CN, CN, CF, CF,
        1, (long long)CNN, 0, (long long)CN*CF, 0, (long long)CN*CF, 0);

    // h2 = h1 @ gc1_w^T   (1024 x 512 x 1024)   [gc1_b cancels in BN]
    gemm_t<true><<<dim3(CHID/128, (CB*CN)/64, 1), 128>>>(
        h1, gc1w, h2, CF, CF, CF, CHID, 1, 0,0, 0,0, 0,0);

    k_bnstats<<<(CB*CN)/32, CHID>>>(h2, CHID, bs1, bq1);
    k_bnfinal<<<1, CHID>>>(bs1, bq1, bn1g, bn1b, sc1, sh1);
    k_bnrelu<<<256, 256>>>(h2, CHID-1, CB*CN*CHID, sc1, sh1);

    // h3 = cm @ h2    (per batch 512x512x512)
    gemm_t<false><<<dim3(CHID/128, CN/64, CB), 128>>>(
        cm, h2, h3, CN, CN, CHID, CHID,
        1, (long long)CNN, 0, (long long)CN*CHID, 0, (long long)CN*CHID, 0);

    // h4 = h3 @ gc2_w^T   (1024 x 128 x 512)    [gc2_b cancels in BN]
    gemm_t<true><<<dim3(COUT/128, (CB*CN)/64, 1), 128>>>(
        h3, gc2w, h4, CHID, CHID, CHID, COUT, 1, 0,0, 0,0, 0,0);

    k_bnstats<<<(CB*CN)/32, COUT>>>(h4, COUT, bs2, bq2);
    k_bnfinal<<<1, COUT>>>(bs2, bq2, bn2g, bn2b, sc2, sh2);

    k_feat<<<CB, COUT>>>();
    k_cls<<<1, 640>>>(clsw, clsb, out);
}